// round 14
// baseline (speedup 1.0000x reference)
#include <cuda_runtime.h>

typedef unsigned long long u64;
typedef unsigned int u32;

#define FMA2(d,a,b,c)  asm("fma.rn.f32x2 %0, %1, %2, %3;" : "=l"(d) : "l"(a), "l"(b), "l"(c))
#define PACK2(d,x,y)   asm("mov.b64 %0, {%1,%2};" : "=l"(d) : "f"(x), "f"(y))
#define UNPACK2(x,y,d) asm("mov.b64 {%0,%1}, %2;" : "=f"(x), "=f"(y) : "l"(d))
#define CVTH2(h,la,lb) asm("cvt.rn.f16x2.f32 %0, %1, %2;" : "=r"(h) : "f"(lb), "f"(la))
#define TANH2H(d,a)    asm("tanh.approx.f16x2 %0, %1;" : "=r"(d) : "r"(a))
#define HFMA2(d,a,b,c) asm("fma.rn.f16x2 %0, %1, %2, %3;" : "=r"(d) : "r"(a), "r"(b), "r"(c))
#define H2TOF2(x,y,h)  asm("{ .reg .f16 lo, hi;\n\t mov.b32 {lo, hi}, %2;\n\t" \
                           "  cvt.f32.f16 %0, lo;\n\t cvt.f32.f16 %1, hi; }" \
                           : "=f"(x), "=f"(y) : "r"(h))
#define CP16O(dst,doff,src,soff) \
    asm volatile("cp.async.cg.shared.global [%0+" #doff "], [%1+" #soff "], 16;" \
                 :: "r"(dst), "l"(src))
#define CPCOMMIT()     asm volatile("cp.async.commit_group;")
#define CPWAIT1()      asm volatile("cp.async.wait_group 1;")

// K converted to f16, [b][j][c] layout, c-pairs packed in u32 (lo = even ch)
__device__ __align__(16) u32 Kh_buf[2 * 1024 * 32];

// ---------------- Kernel A: convert K f32 -> f16 ----------------
__global__ void convert_k_kernel(const float* __restrict__ K)
{
    int i = blockIdx.x * 256 + threadIdx.x;    // 65536 half2 words
    float2 v = ((const float2*)K)[i];
    u32 h; CVTH2(h, v.x, v.y);
    Kh_buf[i] = h;
}

// ---------------- Kernel B: sigmoid masked-mean (output 0) ----------------
#define TILEB_B 4608      // 32 rows x 144B (128B data + 16B pad), 16B-aligned

__global__ __launch_bounds__(128, 5)
void sigmoid_mean_kernel(const float* __restrict__ Q, const float* __restrict__ bias,
                         const float* __restrict__ mask, float* __restrict__ out)
{
    __shared__ __align__(16) char kbs[3][TILEB_B];   // f16 K tile ring
    __shared__ float red[512];
    __shared__ float cbuf[2][4];

    const int tid = threadIdx.x;
    const int w   = tid >> 5, l = tid & 31;
    const int jl  = w * 8 + (l & 7);     // j within tile (0..31)
    const int cg  = l >> 3;              // channel group (16 ch each)

    const int row0 = blockIdx.x * 2;     // two i-rows per block
    const int b    = row0 >> 10;

    // f16x2 q (prescaled 0.5: sigmoid = 0.5 + 0.5*tanh(x/2)), bias likewise
    u32 qh0[8], qh1[8], bh[8], h0[8], h1[8];
    {
        const float* q0p = Q + (size_t)row0 * 64 + cg * 16;
        const float* q1p = q0p + 64;
        const float* bp  = bias + cg * 16;
#pragma unroll
        for (int p = 0; p < 8; ++p) {
            CVTH2(qh0[p], 0.5f * q0p[2*p], 0.5f * q0p[2*p+1]);
            CVTH2(qh1[p], 0.5f * q1p[2*p], 0.5f * q1p[2*p+1]);
            CVTH2(bh[p],  0.5f * bp[2*p],  0.5f * bp[2*p+1]);
            h0[p] = 0u; h1[p] = 0u;
        }
    }
    float cnt0 = 0.f, cnt1 = 0.f;

    const float* m0p = mask + (size_t)row0 * 1024;
    const float* m1p = m0p + 1024;

    // staging: 2 x 16B chunks per thread per tile (f16 tile = 4KB data)
    const u32 smbase = (u32)__cvta_generic_to_shared(kbs);
    const u32 dst0   = smbase + (u32)((tid >> 3) * 144 + (tid & 7) * 16);
    const char* src  = (const char*)Kh_buf + b * 131072
                       + (tid >> 3) * 128 + (tid & 7) * 16;

    // prologue: tiles 0 and 1
#pragma unroll
    for (int t = 0; t < 2; ++t) {
        u32 d = dst0 + t * TILEB_B;
        const char* s = src + t * 4096;
        CP16O(d, 0,    s, 0);
        CP16O(d, 2304, s, 2048);    // +16 rows: dst +16*144, src +16*128
        CPCOMMIT();
    }
    src += 2 * 4096;

    int buf = 0, nb = 2;
    for (int tile = 0; tile < 32; ++tile) {
        CPWAIT1();
        __syncthreads();

        if (tile + 2 < 32) {
            u32 d = dst0 + nb * TILEB_B;
            CP16O(d, 0,    src, 0);
            CP16O(d, 2304, src, 2048);
        }
        CPCOMMIT();
        src += 4096;

        // 16 f16 channels for this thread's j: 2 x LDS.128, conflict-free
        const uint4* kb = (const uint4*)(kbs[buf] + jl * 144 + cg * 32);
        uint4 ka = kb[0], kc = kb[1];
        u32 kh[8] = {ka.x, ka.y, ka.z, ka.w, kc.x, kc.y, kc.z, kc.w};

        const int   j  = tile * 32 + jl;
        const float m0 = m0p[j], m1 = m1p[j];
        u32 m0h, m1h;
        CVTH2(m0h, m0, m0);
        CVTH2(m1h, m1, m1);

#pragma unroll
        for (int p = 0; p < 8; ++p) {
            u32 lh, th;
            HFMA2(lh, qh0[p], kh[p], bh[p]);     // f16 logit (x/2)
            TANH2H(th, lh);                      // one XU inst, two channels
            HFMA2(h0[p], m0h, th, h0[p]);        // f16 accumulate
            HFMA2(lh, qh1[p], kh[p], bh[p]);
            TANH2H(th, lh);
            HFMA2(h1[p], m1h, th, h1[p]);
        }
        if (cg == 0) { cnt0 += m0; cnt1 += m1; }

        buf = (buf == 2) ? 0 : buf + 1;
        nb  = (nb  == 2) ? 0 : nb + 1;
    }

    // ---- final reductions (R12 pattern) ----
#pragma unroll
    for (int p = 0; p < 8; ++p) {
        float x0, y0, x1, y1;
        H2TOF2(x0, y0, h0[p]);
        H2TOF2(x1, y1, h1[p]);
#pragma unroll
        for (int o = 1; o <= 4; o <<= 1) {
            x0 += __shfl_xor_sync(~0u, x0, o);
            y0 += __shfl_xor_sync(~0u, y0, o);
            x1 += __shfl_xor_sync(~0u, x1, o);
            y1 += __shfl_xor_sync(~0u, y1, o);
        }
        if ((l & 7) == 0) {
            float* rp = red + w * 128 + cg * 32;
            rp[2*p]          = x0;
            rp[2*p + 1]      = y0;
            rp[16 + 2*p]     = x1;
            rp[16 + 2*p + 1] = y1;
        }
    }
    for (int o = 1; o <= 4; o <<= 1) {
        cnt0 += __shfl_xor_sync(~0u, cnt0, o);
        cnt1 += __shfl_xor_sync(~0u, cnt1, o);
    }
    if (l == 0) { cbuf[0][w] = cnt0; cbuf[1][w] = cnt1; }
    __syncthreads();

    {
        const int r  = tid >> 6;
        const int ch = tid & 63;
        float ct = cbuf[r][0] + cbuf[r][1] + cbuf[r][2] + cbuf[r][3];
        float s  = 0.f;
#pragma unroll
        for (int ww = 0; ww < 4; ++ww)
            s += red[ww * 128 + (ch >> 4) * 32 + r * 16 + (ch & 15)];
        out[(size_t)(row0 + r) * 64 + ch] = 0.5f + 0.5f * s / ct;
    }
}

// ---------------- Kernel C: attention logits (output 1), exact f32 ----------------
#define TILEB_C 8704      // 32 rows x 17 float4

__global__ __launch_bounds__(128, 3)
void attn_kernel(const float* __restrict__ Q, const float* __restrict__ K,
                 const float* __restrict__ mask, float* __restrict__ attn)
{
    __shared__ float4 ksm[3][32 * 17];   // f32 K tile ring, pad 17

    const int tid = threadIdx.x;
    const int w   = tid >> 5, l = tid & 31;
    const int jl  = w * 8 + (l & 7);
    const int cg  = l >> 3;

    const int row0 = blockIdx.x * 4;     // four i-rows per block
    const int b    = row0 >> 10;

    // q for 4 rows, f32x2 packed: 32 u64
    u64 q2[32];
#pragma unroll
    for (int r = 0; r < 4; ++r) {
        const float* qp = Q + (size_t)(row0 + r) * 64 + cg * 16;
#pragma unroll
        for (int p = 0; p < 8; ++p)
            PACK2(q2[r * 8 + p], qp[2*p], qp[2*p+1]);
    }
    const float* mr0 = mask + (size_t)row0 * 1024;
    float*       ar0 = attn + (size_t)row0 * 1024;

    const u32 smbase = (u32)__cvta_generic_to_shared(ksm);
    const u32 dst0   = smbase + (u32)((((tid >> 4) * 17 + (tid & 15))) << 4);
    const char* src  = (const char*)K + (size_t)b * (1024 * 256)
                       + (((tid >> 4) * 16 + (tid & 15)) << 4);

#pragma unroll
    for (int t = 0; t < 2; ++t) {
        u32 d = dst0 + t * TILEB_C;
        const char* s = src + t * 8192;
        CP16O(d, 0,    s, 0);
        CP16O(d, 2176, s, 2048);
        CP16O(d, 4352, s, 4096);
        CP16O(d, 6528, s, 6144);
        CPCOMMIT();
    }
    src += 2 * 8192;

    int buf = 0, nb = 2;
    for (int tile = 0; tile < 32; ++tile) {
        CPWAIT1();
        __syncthreads();

        if (tile + 2 < 32) {
            u32 d = dst0 + nb * TILEB_C;
            CP16O(d, 0,    src, 0);
            CP16O(d, 2176, src, 2048);
            CP16O(d, 4352, src, 4096);
            CP16O(d, 6528, src, 6144);
        }
        CPCOMMIT();
        src += 8192;

        const u64* kb = (const u64*)(ksm[buf]) + jl * 34 + cg * 8;
        u64 k2[8];
#pragma unroll
        for (int p = 0; p < 8; ++p) k2[p] = kb[p];

        u64 dp0 = 0ull, dp1 = 0ull, dp2 = 0ull, dp3 = 0ull;
#pragma unroll
        for (int p = 0; p < 8; ++p) {
            FMA2(dp0, q2[p],      k2[p], dp0);
            FMA2(dp1, q2[8 + p],  k2[p], dp1);
            FMA2(dp2, q2[16 + p], k2[p], dp2);
            FMA2(dp3, q2[24 + p], k2[p], dp3);
        }

        const int j = tile * 32 + jl;
        float dx, dy, d0, d1, d2, d3;
        UNPACK2(dx, dy, dp0); d0 = dx + dy;
        UNPACK2(dx, dy, dp1); d1 = dx + dy;
        UNPACK2(dx, dy, dp2); d2 = dx + dy;
        UNPACK2(dx, dy, dp3); d3 = dx + dy;
        d0 += __shfl_xor_sync(~0u, d0, 8);  d0 += __shfl_xor_sync(~0u, d0, 16);
        d1 += __shfl_xor_sync(~0u, d1, 8);  d1 += __shfl_xor_sync(~0u, d1, 16);
        d2 += __shfl_xor_sync(~0u, d2, 8);  d2 += __shfl_xor_sync(~0u, d2, 16);
        d3 += __shfl_xor_sync(~0u, d3, 8);  d3 += __shfl_xor_sync(~0u, d3, 16);
        if (cg == 0) {
            ar0[j]        = d0 * mr0[j];
            ar0[1024 + j] = d1 * mr0[1024 + j];
            ar0[2048 + j] = d2 * mr0[2048 + j];
            ar0[3072 + j] = d3 * mr0[3072 + j];
        }

        buf = (buf == 2) ? 0 : buf + 1;
        nb  = (nb  == 2) ? 0 : nb + 1;
    }
}

extern "C" void kernel_launch(void* const* d_in, const int* in_sizes, int n_in,
                              void* d_out, int out_size)
{
    const float* Q    = (const float*)d_in[0];
    const float* K    = (const float*)d_in[1];
    const float* bias = (const float*)d_in[2];
    const float* mask = (const float*)d_in[3];
    float* out  = (float*)d_out;                       // [B, I, C]
    float* attn = out + (size_t)2 * 1024 * 64;         // [B, I, J]

    convert_k_kernel<<<256, 256>>>(K);                 // A: K -> f16 scratch
    sigmoid_mean_kernel<<<1024, 128>>>(Q, bias, mask, out);   // B
    attn_kernel<<<512, 128>>>(Q, K, mask, attn);              // C
}

// round 15
// speedup vs baseline: 1.1008x; 1.1008x over previous
#include <cuda_runtime.h>

#define THREADS 128
#define Jt 32
#define NT 32          // 1024 / Jt
#define DEPTH 3
#define TILEB (Jt * 17 * 16)     // bytes per smem tile slot

typedef unsigned long long u64;
typedef unsigned int u32;

#define FMA2(d,a,b,c)  asm("fma.rn.f32x2 %0, %1, %2, %3;" : "=l"(d) : "l"(a), "l"(b), "l"(c))
#define PACK2(d,x,y)   asm("mov.b64 %0, {%1,%2};" : "=l"(d) : "f"(x), "f"(y))
#define UNPACK2(x,y,d) asm("mov.b64 {%0,%1}, %2;" : "=f"(x), "=f"(y) : "l"(d))
#define CVTH2(h,la,lb) asm("cvt.rn.f16x2.f32 %0, %1, %2;" : "=r"(h) : "f"(lb), "f"(la))
#define TANH2H(d,a)    asm("tanh.approx.f16x2 %0, %1;" : "=r"(d) : "r"(a))
#define HFMA2(d,a,b,c) asm("fma.rn.f16x2 %0, %1, %2, %3;" : "=r"(d) : "r"(a), "r"(b), "r"(c))
#define H2TOF2(x,y,h)  asm("{ .reg .f16 lo, hi;\n\t mov.b32 {lo, hi}, %2;\n\t" \
                           "  cvt.f32.f16 %0, lo;\n\t cvt.f32.f16 %1, hi; }" \
                           : "=f"(x), "=f"(y) : "r"(h))
// forced-in-loop shared load (prevents ptxas hoisting q back into registers)
#define LDSH64(d,addr) asm volatile("ld.shared.b64 %0, [%1];" : "=l"(d) : "r"(addr))
#define CP16O(dst,doff,src,soff) \
    asm volatile("cp.async.cg.shared.global [%0+" #doff "], [%1+" #soff "], 16;" \
                 :: "r"(dst), "l"(src))
#define CPCOMMIT()     asm volatile("cp.async.commit_group;")
#define CPWAIT1()      asm volatile("cp.async.wait_group 1;")

__global__ __launch_bounds__(THREADS, 6)
void attn_mlp_kernel(const float* __restrict__ Q, const float* __restrict__ K,
                     const float* __restrict__ bias, const float* __restrict__ mask,
                     float* __restrict__ out, float* __restrict__ attn)
{
    __shared__ float4 ksm[DEPTH][Jt * 17];   // f32 K tile ring, pad 17 -> conflict-free
    __shared__ u64    qs[2][8][4];           // raw f32 q pairs [row][pair][cg]
    __shared__ float  red[512];
    __shared__ float  cbuf[2][4];

    const int tid = threadIdx.x;
    const int w   = tid >> 5, l = tid & 31;
    const int jl  = w * 8 + (l & 7);     // j within tile (0..31)
    const int cg  = l >> 3;              // channel group (16 ch each)

    const int row0 = blockIdx.x * 2;     // two i-rows per block, same b
    const int b    = row0 >> 10;

    // stage raw f32 q into smem (one float per thread)
    {
        const int r = tid >> 6, ch = tid & 63;
        ((float*)qs)[(((r * 8 + ((ch & 15) >> 1)) * 4 + (ch >> 4)) << 1) + (ch & 1)]
            = Q[(size_t)(row0 + r) * 64 + ch];
    }

    // f16 q (prescaled 0.5: sigmoid = 0.5 + 0.5*tanh(x/2)) and bias; f16x2 accumulators
    u32 qh0[8], qh1[8], bh[8], h0[8], h1[8];
    {
        const float* q0p = Q + (size_t)row0 * 64 + cg * 16;
        const float* q1p = q0p + 64;
        const float* bp  = bias + cg * 16;
#pragma unroll
        for (int p = 0; p < 8; ++p) {
            CVTH2(qh0[p], 0.5f * q0p[2*p], 0.5f * q0p[2*p+1]);
            CVTH2(qh1[p], 0.5f * q1p[2*p], 0.5f * q1p[2*p+1]);
            CVTH2(bh[p],  0.5f * bp[2*p],  0.5f * bp[2*p+1]);
            h0[p] = 0u; h1[p] = 0u;
        }
    }
    float cnt0 = 0.f, cnt1 = 0.f;

    const float* m0p = mask + (size_t)row0 * 1024;
    const float* m1p = m0p + 1024;
    float*       a0p = attn + (size_t)row0 * 1024;
    float*       a1p = a0p + 1024;

    // cp.async staging: 4 float4/thread/tile; dst base + src ptr, imm offsets
    const u32 smbase = (u32)__cvta_generic_to_shared(ksm);
    const u32 qbase0 = (u32)__cvta_generic_to_shared(qs) + cg * 8;   // [0][p][cg]
    const u32 dst0   = smbase + (u32)((((tid >> 4) * 17 + (tid & 15))) << 4);
    const char* src  = (const char*)K + (size_t)b * (1024 * 256)
                       + (((tid >> 4) * 16 + (tid & 15)) << 4);

    // prologue: tiles 0 and 1 (two groups)
#pragma unroll
    for (int t = 0; t < 2; ++t) {
        u32 d = dst0 + t * TILEB;
        const char* s = src + t * 8192;
        CP16O(d, 0,    s, 0);
        CP16O(d, 2176, s, 2048);
        CP16O(d, 4352, s, 4096);
        CP16O(d, 6528, s, 6144);
        CPCOMMIT();
    }
    src += 2 * 8192;

    int buf = 0, nb = 2;
    for (int tile = 0; tile < NT; ++tile) {
        CPWAIT1();            // this tile's group complete (<=1 newer pending)
        __syncthreads();      // also orders the qs stores on tile 0

        // prefetch tile+2 into ring slot nb (empty commit keeps group count in sync)
        if (tile + 2 < NT) {
            u32 d = dst0 + nb * TILEB;
            CP16O(d, 0,    src, 0);
            CP16O(d, 2176, src, 2048);
            CP16O(d, 4352, src, 4096);
            CP16O(d, 6528, src, 6144);
        }
        CPCOMMIT();
        src += 8192;

        const u64* kb = (const u64*)(ksm[buf]) + jl * 34 + cg * 8;
        const int   j  = tile * Jt + jl;
        const float m0 = m0p[j], m1 = m1p[j];
        u32 m0h, m1h;
        CVTH2(m0h, m0, m0);
        CVTH2(m1h, m1, m1);
        u64 dp0 = 0ull, dp1 = 0ull;

#pragma unroll
        for (int p = 0; p < 8; ++p) {
            u64 k2 = kb[p];                      // f32 channel pair
            float kx, ky; u32 kh;
            UNPACK2(kx, ky, k2);
            CVTH2(kh, kx, ky);                   // f16 copy for sigmoid path
            u64 q20, q21;
            LDSH64(q20, qbase0 + p * 32);        // raw f32 q pairs from smem
            LDSH64(q21, qbase0 + 256 + p * 32);
            FMA2(dp0, q20, k2, dp0);             // exact f32 dot partials
            FMA2(dp1, q21, k2, dp1);
            u32 lh, th;
            HFMA2(lh, qh0[p], kh, bh[p]);        // f16 logit (x/2), 4-cyc op
            TANH2H(th, lh);                      // one XU inst, two channels
            HFMA2(h0[p], m0h, th, h0[p]);
            HFMA2(lh, qh1[p], kh, bh[p]);
            TANH2H(th, lh);
            HFMA2(h1[p], m1h, th, h1[p]);
        }
        if (cg == 0) { cnt0 += m0; cnt1 += m1; }

        // attention logits: raw q -> attn = dot * mask (exact fp32 path)
        float dx, dy;
        UNPACK2(dx, dy, dp0); float d0 = dx + dy;
        UNPACK2(dx, dy, dp1); float d1 = dx + dy;
        d0 += __shfl_xor_sync(~0u, d0, 8);
        d0 += __shfl_xor_sync(~0u, d0, 16);
        d1 += __shfl_xor_sync(~0u, d1, 8);
        d1 += __shfl_xor_sync(~0u, d1, 16);
        if (cg == 0) {
            a0p[j] = d0 * m0;
            a1p[j] = d1 * m1;
        }
        buf = (buf == DEPTH - 1) ? 0 : buf + 1;
        nb  = (nb  == DEPTH - 1) ? 0 : nb + 1;
    }

    // ---- final reductions ----
#pragma unroll
    for (int p = 0; p < 8; ++p) {
        float x0, y0, x1, y1;
        H2TOF2(x0, y0, h0[p]);
        H2TOF2(x1, y1, h1[p]);
#pragma unroll
        for (int o = 1; o <= 4; o <<= 1) {
            x0 += __shfl_xor_sync(~0u, x0, o);
            y0 += __shfl_xor_sync(~0u, y0, o);
            x1 += __shfl_xor_sync(~0u, x1, o);
            y1 += __shfl_xor_sync(~0u, y1, o);
        }
        if ((l & 7) == 0) {
            float* rp = red + w * 128 + cg * 32;
            rp[2*p]          = x0;
            rp[2*p + 1]      = y0;
            rp[16 + 2*p]     = x1;
            rp[16 + 2*p + 1] = y1;
        }
    }
    for (int o = 1; o <= 4; o <<= 1) {
        cnt0 += __shfl_xor_sync(~0u, cnt0, o);
        cnt1 += __shfl_xor_sync(~0u, cnt1, o);
    }
    if (l == 0) { cbuf[0][w] = cnt0; cbuf[1][w] = cnt1; }
    __syncthreads();

    {
        const int r  = tid >> 6;
        const int ch = tid & 63;
        float ct = cbuf[r][0] + cbuf[r][1] + cbuf[r][2] + cbuf[r][3];
        float s  = 0.f;
#pragma unroll
        for (int ww = 0; ww < 4; ++ww)
            s += red[ww * 128 + (ch >> 4) * 32 + r * 16 + (ch & 15)];
        out[(size_t)(row0 + r) * 64 + ch] = 0.5f + 0.5f * s / ct;
    }
}

extern "C" void kernel_launch(void* const* d_in, const int* in_sizes, int n_in,
                              void* d_out, int out_size)
{
    const float* Q    = (const float*)d_in[0];
    const float* K    = (const float*)d_in[1];
    const float* bias = (const float*)d_in[2];
    const float* mask = (const float*)d_in[3];
    float* out  = (float*)d_out;                       // [B, I, C]
    float* attn = out + (size_t)2 * 1024 * 64;         // [B, I, J]
    attn_mlp_kernel<<<1024, THREADS>>>(Q, K, bias, mask, out, attn);
}

// round 16
// speedup vs baseline: 1.2972x; 1.1785x over previous
#include <cuda_runtime.h>

#define THREADS 128
#define Jt 32
#define NT 32          // 1024 / Jt
#define DEPTH 3
#define TILEB (Jt * 17 * 16)     // bytes per smem tile slot

typedef unsigned long long u64;
typedef unsigned int u32;

#define FMA2(d,a,b,c)  asm("fma.rn.f32x2 %0, %1, %2, %3;" : "=l"(d) : "l"(a), "l"(b), "l"(c))
#define PACK2(d,x,y)   asm("mov.b64 %0, {%1,%2};" : "=l"(d) : "f"(x), "f"(y))
#define UNPACK2(x,y,d) asm("mov.b64 {%0,%1}, %2;" : "=f"(x), "=f"(y) : "l"(d))
#define CVTH2(h,la,lb) asm("cvt.rn.f16x2.f32 %0, %1, %2;" : "=r"(h) : "f"(lb), "f"(la))
#define TANH2H(d,a)    asm("tanh.approx.f16x2 %0, %1;" : "=r"(d) : "r"(a))
#define HFMA2(d,a,b,c) asm("fma.rn.f16x2 %0, %1, %2, %3;" : "=r"(d) : "r"(a), "r"(b), "r"(c))
#define H2TOF2(x,y,h)  asm("{ .reg .f16 lo, hi;\n\t mov.b32 {lo, hi}, %2;\n\t" \
                           "  cvt.f32.f16 %0, lo;\n\t cvt.f32.f16 %1, hi; }" \
                           : "=f"(x), "=f"(y) : "r"(h))
// LDS.128 as two u64 (keeps pairs in 64-bit regs for FMA2)
#define LDS2U64(a,b,addr) asm("ld.shared.v2.u64 {%0,%1}, [%2];" : "=l"(a), "=l"(b) : "r"(addr))
#define CP16O(dst,doff,src,soff) \
    asm volatile("cp.async.cg.shared.global [%0+" #doff "], [%1+" #soff "], 16;" \
                 :: "r"(dst), "l"(src))
#define CPCOMMIT()     asm volatile("cp.async.commit_group;")
#define CPWAIT1()      asm volatile("cp.async.wait_group 1;")

__global__ __launch_bounds__(THREADS, 4)
void attn_mlp_kernel(const float* __restrict__ Q, const float* __restrict__ K,
                     const float* __restrict__ bias, const float* __restrict__ mask,
                     float* __restrict__ out, float* __restrict__ attn)
{
    __shared__ float4 ksm[DEPTH][Jt * 17];   // f32 K tile ring, pad 17 -> conflict-free
    __shared__ float  red[512];
    __shared__ float  cbuf[2][4];

    const int tid = threadIdx.x;
    const int w   = tid >> 5, l = tid & 31;
    const int jl  = w * 8 + (l & 7);     // j within tile (0..31)
    const int cg  = l >> 3;              // channel group (16 ch each)

    const int row0 = blockIdx.x * 2;     // two i-rows per block, same b
    const int b    = row0 >> 10;

    // f32 q RAW (for exact attention dot); f16x2 q/bias prescaled by 0.5
    // (sigmoid = 0.5 + 0.5*tanh(x/2)); f16x2 accumulators (no flush, |h|<=32)
    u64 q20[8], q21[8];
    u32 qh0[8], qh1[8], bh[8], h0[8], h1[8];
    {
        const float* q0p = Q + (size_t)row0 * 64 + cg * 16;
        const float* q1p = q0p + 64;
        const float* bp  = bias + cg * 16;
#pragma unroll
        for (int p = 0; p < 8; ++p) {
            PACK2(q20[p], q0p[2*p], q0p[2*p+1]);
            PACK2(q21[p], q1p[2*p], q1p[2*p+1]);
            CVTH2(qh0[p], 0.5f * q0p[2*p], 0.5f * q0p[2*p+1]);
            CVTH2(qh1[p], 0.5f * q1p[2*p], 0.5f * q1p[2*p+1]);
            CVTH2(bh[p],  0.5f * bp[2*p],  0.5f * bp[2*p+1]);
            h0[p] = 0u; h1[p] = 0u;
        }
    }
    float cnt0 = 0.f, cnt1 = 0.f;

    const float* m0p = mask + (size_t)row0 * 1024;
    const float* m1p = m0p + 1024;
    float*       a0p = attn + (size_t)row0 * 1024;
    float*       a1p = a0p + 1024;

    // cp.async staging: 4 float4/thread/tile; dst base + src ptr, imm offsets
    const u32 smbase = (u32)__cvta_generic_to_shared(ksm);
    const u32 dst0   = smbase + (u32)((((tid >> 4) * 17 + (tid & 15))) << 4);
    const u32 kaddr0 = smbase + (u32)(jl * 272 + cg * 64);   // this thread's 16 ch
    const char* src  = (const char*)K + (size_t)b * (1024 * 256)
                       + (((tid >> 4) * 16 + (tid & 15)) << 4);

    // prologue: tiles 0 and 1 (two groups)
#pragma unroll
    for (int t = 0; t < 2; ++t) {
        u32 d = dst0 + t * TILEB;
        const char* s = src + t * 8192;
        CP16O(d, 0,    s, 0);
        CP16O(d, 2176, s, 2048);
        CP16O(d, 4352, s, 4096);
        CP16O(d, 6528, s, 6144);
        CPCOMMIT();
    }
    src += 2 * 8192;

    int buf = 0, nb = 2;
    for (int tile = 0; tile < NT; ++tile) {
        CPWAIT1();            // this tile's group complete (<=1 newer pending)
        __syncthreads();

        // prefetch tile+2 into ring slot nb (empty commit keeps group count in sync)
        if (tile + 2 < NT) {
            u32 d = dst0 + nb * TILEB;
            CP16O(d, 0,    src, 0);
            CP16O(d, 2176, src, 2048);
            CP16O(d, 4352, src, 4096);
            CP16O(d, 6528, src, 6144);
        }
        CPCOMMIT();
        src += 8192;

        // 16 channels for this thread's j: 4 x LDS.128 (conflict-free, padded rows)
        const u32 ka = kaddr0 + buf * TILEB;
        u64 k2[8];
        LDS2U64(k2[0], k2[1], ka);
        LDS2U64(k2[2], k2[3], ka + 16);
        LDS2U64(k2[4], k2[5], ka + 32);
        LDS2U64(k2[6], k2[7], ka + 48);

        const int   j  = tile * Jt + jl;
        const float m0 = m0p[j], m1 = m1p[j];
        u32 m0h, m1h;
        CVTH2(m0h, m0, m0);
        CVTH2(m1h, m1, m1);
        u64 dp0 = 0ull, dp1 = 0ull;

#pragma unroll
        for (int p = 0; p < 8; ++p) {
            float kx, ky; u32 kh, lh, th;
            UNPACK2(kx, ky, k2[p]);              // free (register aliasing)
            CVTH2(kh, kx, ky);                   // one f16 copy of k per pair
            FMA2(dp0, q20[p], k2[p], dp0);       // exact f32 dot partials
            FMA2(dp1, q21[p], k2[p], dp1);
            HFMA2(lh, qh0[p], kh, bh[p]);        // f16 logit (x/2)
            TANH2H(th, lh);                      // one XU inst, two channels
            HFMA2(h0[p], m0h, th, h0[p]);        // f16 accumulate
            HFMA2(lh, qh1[p], kh, bh[p]);
            TANH2H(th, lh);
            HFMA2(h1[p], m1h, th, h1[p]);
        }
        if (cg == 0) { cnt0 += m0; cnt1 += m1; }

        // attention logits: raw q -> attn = dot * mask (exact fp32 path)
        float dx, dy;
        UNPACK2(dx, dy, dp0); float d0 = dx + dy;
        UNPACK2(dx, dy, dp1); float d1 = dx + dy;
        d0 += __shfl_xor_sync(~0u, d0, 8);
        d0 += __shfl_xor_sync(~0u, d0, 16);
        d1 += __shfl_xor_sync(~0u, d1, 8);
        d1 += __shfl_xor_sync(~0u, d1, 16);
        if (cg == 0) {
            a0p[j] = d0 * m0;
            a1p[j] = d1 * m1;
        }
        buf = (buf == DEPTH - 1) ? 0 : buf + 1;
        nb  = (nb  == DEPTH - 1) ? 0 : nb + 1;
    }

    // ---- final reductions (R12 pattern) ----
#pragma unroll
    for (int p = 0; p < 8; ++p) {
        float x0, y0, x1, y1;
        H2TOF2(x0, y0, h0[p]);
        H2TOF2(x1, y1, h1[p]);
#pragma unroll
        for (int o = 1; o <= 4; o <<= 1) {
            x0 += __shfl_xor_sync(~0u, x0, o);
            y0 += __shfl_xor_sync(~0u, y0, o);
            x1 += __shfl_xor_sync(~0u, x1, o);
            y1 += __shfl_xor_sync(~0u, y1, o);
        }
        if ((l & 7) == 0) {
            float* rp = red + w * 128 + cg * 32;
            rp[2*p]          = x0;
            rp[2*p + 1]      = y0;
            rp[16 + 2*p]     = x1;
            rp[16 + 2*p + 1] = y1;
        }
    }
    for (int o = 1; o <= 4; o <<= 1) {
        cnt0 += __shfl_xor_sync(~0u, cnt0, o);
        cnt1 += __shfl_xor_sync(~0u, cnt1, o);
    }
    if (l == 0) { cbuf[0][w] = cnt0; cbuf[1][w] = cnt1; }
    __syncthreads();

    {
        const int r  = tid >> 6;
        const int ch = tid & 63;
        float ct = cbuf[r][0] + cbuf[r][1] + cbuf[r][2] + cbuf[r][3];
        float s  = 0.f;
#pragma unroll
        for (int ww = 0; ww < 4; ++ww)
            s += red[ww * 128 + (ch >> 4) * 32 + r * 16 + (ch & 15)];
        out[(size_t)(row0 + r) * 64 + ch] = 0.5f + 0.5f * s / ct;
    }
}

extern "C" void kernel_launch(void* const* d_in, const int* in_sizes, int n_in,
                              void* d_out, int out_size)
{
    const float* Q    = (const float*)d_in[0];
    const float* K    = (const float*)d_in[1];
    const float* bias = (const float*)d_in[2];
    const float* mask = (const float*)d_in[3];
    float* out  = (float*)d_out;                       // [B, I, C]
    float* attn = out + (size_t)2 * 1024 * 64;         // [B, I, J]
    attn_mlp_kernel<<<1024, THREADS>>>(Q, K, bias, mask, out, attn);
}

// round 17
// speedup vs baseline: 1.3434x; 1.0356x over previous
#include <cuda_runtime.h>

#define THREADS 128
#define Jt 32
#define NT 32          // 1024 / Jt
#define DEPTH 3
#define TILEB (Jt * 17 * 16)     // bytes per K smem tile slot

typedef unsigned long long u64;
typedef unsigned int u32;

#define FMA2(d,a,b,c)  asm("fma.rn.f32x2 %0, %1, %2, %3;" : "=l"(d) : "l"(a), "l"(b), "l"(c))
#define PACK2(d,x,y)   asm("mov.b64 %0, {%1,%2};" : "=l"(d) : "f"(x), "f"(y))
#define UNPACK2(x,y,d) asm("mov.b64 {%0,%1}, %2;" : "=f"(x), "=f"(y) : "l"(d))
#define CVTH2(h,la,lb) asm("cvt.rn.f16x2.f32 %0, %1, %2;" : "=r"(h) : "f"(lb), "f"(la))
#define TANH2H(d,a)    asm("tanh.approx.f16x2 %0, %1;" : "=r"(d) : "r"(a))
#define HFMA2(d,a,b,c) asm("fma.rn.f16x2 %0, %1, %2, %3;" : "=r"(d) : "r"(a), "r"(b), "r"(c))
#define H2TOF2(x,y,h)  asm("{ .reg .f16 lo, hi;\n\t mov.b32 {lo, hi}, %2;\n\t" \
                           "  cvt.f32.f16 %0, lo;\n\t cvt.f32.f16 %1, hi; }" \
                           : "=f"(x), "=f"(y) : "r"(h))
#define LDS2U64(a,b,addr) asm("ld.shared.v2.u64 {%0,%1}, [%2];" : "=l"(a), "=l"(b) : "r"(addr))
#define CP16O(dst,doff,src,soff) \
    asm volatile("cp.async.cg.shared.global [%0+" #doff "], [%1+" #soff "], 16;" \
                 :: "r"(dst), "l"(src))
#define CPCOMMIT()     asm volatile("cp.async.commit_group;")
#define CPWAIT1()      asm volatile("cp.async.wait_group 1;")

__global__ __launch_bounds__(THREADS, 4)
void attn_mlp_kernel(const float* __restrict__ Q, const float* __restrict__ K,
                     const float* __restrict__ bias, const float* __restrict__ mask,
                     float* __restrict__ out, float* __restrict__ attn)
{
    __shared__ float4 ksm[DEPTH][Jt * 17];   // f32 K tile ring, pad 17 -> conflict-free
    __shared__ float  msm[DEPTH][64];        // mask ring: [slot][row*32 + j]
    __shared__ float  red[512];
    __shared__ float  cbuf[2][4];

    const int tid = threadIdx.x;
    const int w   = tid >> 5, l = tid & 31;
    const int jl  = w * 8 + (l & 7);     // j within tile (0..31)
    const int cg  = l >> 3;              // channel group (16 ch each)

    const int row0 = blockIdx.x * 2;     // two i-rows per block, same b
    const int b    = row0 >> 10;

    // f32 q RAW (exact attention dot); f16x2 q/bias prescaled by 0.5
    // (sigmoid = 0.5 + 0.5*tanh(x/2)); f16x2 accumulators (|h| <= 32, no flush)
    u64 q20[8], q21[8];
    u32 qh0[8], qh1[8], bh[8], h0[8], h1[8];
    {
        const float* q0p = Q + (size_t)row0 * 64 + cg * 16;
        const float* q1p = q0p + 64;
        const float* bp  = bias + cg * 16;
#pragma unroll
        for (int p = 0; p < 8; ++p) {
            PACK2(q20[p], q0p[2*p], q0p[2*p+1]);
            PACK2(q21[p], q1p[2*p], q1p[2*p+1]);
            CVTH2(qh0[p], 0.5f * q0p[2*p], 0.5f * q0p[2*p+1]);
            CVTH2(qh1[p], 0.5f * q1p[2*p], 0.5f * q1p[2*p+1]);
            CVTH2(bh[p],  0.5f * bp[2*p],  0.5f * bp[2*p+1]);
            h0[p] = 0u; h1[p] = 0u;
        }
    }
    float cnt0 = 0.f, cnt1 = 0.f;

    float* a0p = attn + (size_t)row0 * 1024;
    float* a1p = a0p + 1024;

    // cp.async staging: K = 4 float4/thread/tile; mask = 16 threads x 16B/tile
    const u32 smbase = (u32)__cvta_generic_to_shared(ksm);
    const u32 mbase  = (u32)__cvta_generic_to_shared(msm);
    const u32 dst0   = smbase + (u32)((((tid >> 4) * 17 + (tid & 15))) << 4);
    const u32 mdst0  = mbase + (u32)((tid >> 3) * 128 + (tid & 7) * 16);   // tid<16
    const char* src  = (const char*)K + (size_t)b * (1024 * 256)
                       + (((tid >> 4) * 16 + (tid & 15)) << 4);
    const char* msrc = (const char*)mask + (size_t)row0 * 4096
                       + (tid >> 3) * 4096 + (tid & 7) * 16;               // tid<16

    // prologue: tiles 0 and 1 (two groups; mask chunks ride the same groups)
#pragma unroll
    for (int t = 0; t < 2; ++t) {
        u32 d = dst0 + t * TILEB;
        const char* s = src + t * 8192;
        CP16O(d, 0,    s, 0);
        CP16O(d, 2176, s, 2048);
        CP16O(d, 4352, s, 4096);
        CP16O(d, 6528, s, 6144);
        if (tid < 16)
            CP16O(mdst0 + t * 256, 0, msrc + t * 128, 0);
        CPCOMMIT();
    }
    src  += 2 * 8192;
    msrc += 2 * 128;

    int buf = 0, nb = 2;
    for (int tile = 0; tile < NT; ++tile) {
        CPWAIT1();            // this tile's group complete (<=1 newer pending)
        __syncthreads();

        // prefetch tile+2 (K + mask) into ring slot nb; empty commit keeps count in sync
        if (tile + 2 < NT) {
            u32 d = dst0 + nb * TILEB;
            CP16O(d, 0,    src, 0);
            CP16O(d, 2176, src, 2048);
            CP16O(d, 4352, src, 4096);
            CP16O(d, 6528, src, 6144);
            if (tid < 16)
                CP16O(mdst0 + nb * 256, 0, msrc, 0);
        }
        CPCOMMIT();
        src  += 8192;
        msrc += 128;

        // 16 channels for this thread's j: 4 x LDS.128 (conflict-free, padded rows)
        const u32 ka = smbase + (u32)(jl * 272 + cg * 64) + buf * TILEB;
        u64 k2[8];
        LDS2U64(k2[0], k2[1], ka);
        LDS2U64(k2[2], k2[3], ka + 16);
        LDS2U64(k2[4], k2[5], ka + 32);
        LDS2U64(k2[6], k2[7], ka + 48);

        // mask from smem ring (broadcast LDS, latency covered by the ring)
        const float m0 = msm[buf][jl];
        const float m1 = msm[buf][32 + jl];
        u32 m0h, m1h;
        CVTH2(m0h, m0, m0);
        CVTH2(m1h, m1, m1);
        u64 dp0 = 0ull, dp1 = 0ull;

#pragma unroll
        for (int p = 0; p < 8; ++p) {
            float kx, ky; u32 kh, lh, th;
            UNPACK2(kx, ky, k2[p]);              // register aliasing, ~free
            CVTH2(kh, kx, ky);                   // one f16 copy of k per pair
            FMA2(dp0, q20[p], k2[p], dp0);       // exact f32 dot partials
            FMA2(dp1, q21[p], k2[p], dp1);
            HFMA2(lh, qh0[p], kh, bh[p]);        // f16 logit (x/2)
            TANH2H(th, lh);                      // one XU inst, two channels
            HFMA2(h0[p], m0h, th, h0[p]);        // f16 accumulate
            HFMA2(lh, qh1[p], kh, bh[p]);
            TANH2H(th, lh);
            HFMA2(h1[p], m1h, th, h1[p]);
        }
        if (cg == 0) { cnt0 += m0; cnt1 += m1; }

        // attention logits: raw q -> attn = dot * mask (exact fp32 path)
        const int j = tile * Jt + jl;
        float dx, dy;
        UNPACK2(dx, dy, dp0); float d0 = dx + dy;
        UNPACK2(dx, dy, dp1); float d1 = dx + dy;
        d0 += __shfl_xor_sync(~0u, d0, 8);
        d0 += __shfl_xor_sync(~0u, d0, 16);
        d1 += __shfl_xor_sync(~0u, d1, 8);
        d1 += __shfl_xor_sync(~0u, d1, 16);
        if (cg == 0) {
            a0p[j] = d0 * m0;
            a1p[j] = d1 * m1;
        }
        buf = (buf == DEPTH - 1) ? 0 : buf + 1;
        nb  = (nb  == DEPTH - 1) ? 0 : nb + 1;
    }

    // ---- final reductions (R12 pattern) ----
#pragma unroll
    for (int p = 0; p < 8; ++p) {
        float x0, y0, x1, y1;
        H2TOF2(x0, y0, h0[p]);
        H2TOF2(x1, y1, h1[p]);
#pragma unroll
        for (int o = 1; o <= 4; o <<= 1) {
            x0 += __shfl_xor_sync(~0u, x0, o);
            y0 += __shfl_xor_sync(~0u, y0, o);
            x1 += __shfl_xor_sync(~0u, x1, o);
            y1 += __shfl_xor_sync(~0u, y1, o);
        }
        if ((l & 7) == 0) {
            float* rp = red + w * 128 + cg * 32;
            rp[2*p]          = x0;
            rp[2*p + 1]      = y0;
            rp[16 + 2*p]     = x1;
            rp[16 + 2*p + 1] = y1;
        }
    }
    for (int o = 1; o <= 4; o <<= 1) {
        cnt0 += __shfl_xor_sync(~0u, cnt0, o);
        cnt1 += __shfl_xor_sync(~0u, cnt1, o);
    }
    if (l == 0) { cbuf[0][w] = cnt0; cbuf[1][w] = cnt1; }
    __syncthreads();

    {
        const int r  = tid >> 6;
        const int ch = tid & 63;
        float ct = cbuf[r][0] + cbuf[r][1] + cbuf[r][2] + cbuf[r][3];
        float s  = 0.f;
#pragma unroll
        for (int ww = 0; ww < 4; ++ww)
            s += red[ww * 128 + (ch >> 4) * 32 + r * 16 + (ch & 15)];
        out[(size_t)(row0 + r) * 64 + ch] = 0.5f + 0.5f * s / ct;
    }
}

extern "C" void kernel_launch(void* const* d_in, const int* in_sizes, int n_in,
                              void* d_out, int out_size)
{
    const float* Q    = (const float*)d_in[0];
    const float* K    = (const float*)d_in[1];
    const float* bias = (const float*)d_in[2];
    const float* mask = (const float*)d_in[3];
    float* out  = (float*)d_out;                       // [B, I, C]
    float* attn = out + (size_t)2 * 1024 * 64;         // [B, I, J]
    attn_mlp_kernel<<<1024, THREADS>>>(Q, K, bias, mask, out, attn);
}